// round 7
// baseline (speedup 1.0000x reference)
#include <cuda_runtime.h>
#include <cstdint>

// CIN (xDeepFM) via mma.sync tf32 — round 7.
// NBT=14 (grid 293 ~= 2 full waves), 448 threads / 14 warps, warp tile 64h x 32n,
// fragment-ordered W, 3-stage cp.async pipeline with 1 sync per chunk.

#define THREADS 448
#define NBT     14
#define NN      (NBT * 16)   // 224 n-columns per CTA
#define XROW    232          // smem row stride (floats), mod 32 == 8 -> conflict-free

typedef unsigned long long u64;

// Fragment-ordered tf32 weights: [chunk][kstep][htile(8)][lane(32)][4]
__device__ float W0pg[39 * 5 * 8 * 32 * 4];    // layer0: CHUNK=40 (39 real + 1 pad)
__device__ float W1pg[156 * 4 * 8 * 32 * 4];   // layers 1/2: CHUNK=32
__device__ float W2pg[156 * 4 * 8 * 32 * 4];

__device__ __forceinline__ uint32_t smem_u32(const void* p) {
    uint32_t a;
    asm("{ .reg .u64 t; cvta.to.shared.u64 t, %1; cvt.u32.u64 %0, t; }" : "=r"(a) : "l"(p));
    return a;
}
__device__ __forceinline__ float tf32r(float x) {
    uint32_t u; asm("cvt.rna.tf32.f32 %0, %1;" : "=r"(u) : "f"(x));
    return __uint_as_float(u);
}
__device__ __forceinline__ void cp16(uint32_t dst, const float* src) {
    asm volatile("cp.async.cg.shared.global [%0], [%1], 16;" :: "r"(dst), "l"(src) : "memory");
}
__device__ __forceinline__ void mma8(float c[4], const uint32_t a[4], uint32_t b0, uint32_t b1) {
    asm volatile(
        "mma.sync.aligned.m16n8k8.row.col.f32.tf32.tf32.f32 "
        "{%0,%1,%2,%3},{%4,%5,%6,%7},{%8,%9},{%0,%1,%2,%3};"
        : "+f"(c[0]), "+f"(c[1]), "+f"(c[2]), "+f"(c[3])
        : "r"(a[0]), "r"(a[1]), "r"(a[2]), "r"(a[3]), "r"(b0), "r"(b1));
}

// -------------------- weight prep: fragment-order repack ---------------------
__global__ void frag_w(const float* __restrict__ W, float* __restrict__ Wo) {
    int g = blockIdx.x * 256 + threadIdx.x;
    if (g >= 156 * 1024) return;
    int lane = g & 31, ht = (g >> 5) & 7, ks = (g >> 8) & 3, c = g >> 10;
    int grp = lane >> 2, tig = lane & 3;
    int row = ht * 16 + grp;
    int col = c * 32 + ks * 8 + tig;
    float4 v;
    v.x = tf32r(W[(size_t)row * 4992 + col]);
    v.y = tf32r(W[(size_t)(row + 8) * 4992 + col]);
    v.z = tf32r(W[(size_t)row * 4992 + col + 4]);
    v.w = tf32r(W[(size_t)(row + 8) * 4992 + col + 4]);
    ((float4*)Wo)[g] = v;
}
__global__ void frag_w0(const float* __restrict__ W) {
    int g = blockIdx.x * 256 + threadIdx.x;
    if (g >= 39 * 1280) return;
    int lane = g & 31, ht = (g >> 5) & 7;
    int r = g >> 8;              // ks + 5*c
    int ks = r % 5, c = r / 5;
    int grp = lane >> 2, tig = lane & 3;
    int row = ht * 16 + grp;
    int kl = ks * 8 + tig;       // <= 35
    int col = c * 39 + kl;
    float4 v;
    v.x = tf32r(W[(size_t)row * 1521 + col]);
    v.y = tf32r(W[(size_t)(row + 8) * 1521 + col]);
    v.z = (kl + 4 < 39) ? tf32r(W[(size_t)row * 1521 + col + 4]) : 0.f;
    v.w = (kl + 4 < 39) ? tf32r(W[(size_t)(row + 8) * 1521 + col + 4]) : 0.f;
    ((float4*)W0pg)[g] = v;
}

// -------------------- one layer GEMM ----------------------------------------
// 3-stage pipeline, ONE __syncthreads per chunk.
template <int CHUNK, int KSTEPS, int NCH>
__device__ __forceinline__ void layer_mma(
    const float* __restrict__ Wg,
    const float* xi, const float* x0s,
    float* wsm, float acc[4][4][4], int tid)
{
    const int STAGE = 128 * CHUNK;           // floats per stage
    int lane = tid & 31, wid = tid >> 5;
    int grp = lane >> 2, tig = lane & 3;
    int ht_base = (wid & 1) * 4;
    int n_base = (wid >> 1) * 32;

    auto prefetch = [&](int c) {
        if (c < NCH) {
            uint32_t du = smem_u32(wsm + (c % 3) * STAGE);
            const float* src = Wg + (size_t)c * STAGE;
            #pragma unroll
            for (int s = tid; s < STAGE / 4; s += THREADS)
                cp16(du + (uint32_t)s * 16, src + s * 4);
        }
        asm volatile("cp.async.commit_group;" ::: "memory");
    };

    prefetch(0);
    prefetch(1);

    for (int c = 0; c < NCH; c++) {
        asm volatile("cp.async.wait_group 1;" ::: "memory");
        __syncthreads();   // chunk c visible to all warps; all warps done with c-1
        prefetch(c + 2);   // overwrites stage (c-1)%3 — safe after the sync

        const float4* wf = (const float4*)(wsm + (c % 3) * STAGE);
        int j   = (CHUNK == 40) ? c : (c >> 2);
        int kkb = (CHUNK == 40) ? 0 : ((c & 3) * 32);

        float x0v[4];
        #pragma unroll
        for (int nt = 0; nt < 4; nt++)
            x0v[nt] = x0s[j * XROW + n_base + nt * 8 + grp];

        #pragma unroll
        for (int ks = 0; ks < KSTEPS; ks++) {
            uint32_t A[4][4];
            const float4* af = wf + ((ks * 8 + ht_base) * 32 + lane);
            #pragma unroll
            for (int mt = 0; mt < 4; mt++) {
                float4 av = af[mt * 32];
                A[mt][0] = __float_as_uint(av.x);
                A[mt][1] = __float_as_uint(av.y);
                A[mt][2] = __float_as_uint(av.z);
                A[mt][3] = __float_as_uint(av.w);
            }
            int kk = kkb + ks * 8 + tig;
            const float* xlo = xi + kk * XROW + n_base + grp;
            const float* xhi = xlo + 4 * XROW;
            #pragma unroll
            for (int nt = 0; nt < 4; nt++) {
                float p0 = x0v[nt] * xlo[nt * 8];
                float p1 = x0v[nt] * xhi[nt * 8];
                uint32_t B0, B1;
                asm("cvt.rna.tf32.f32 %0, %1;" : "=r"(B0) : "f"(p0));
                asm("cvt.rna.tf32.f32 %0, %1;" : "=r"(B1) : "f"(p1));
                #pragma unroll
                for (int mt = 0; mt < 4; mt++)
                    mma8(acc[mt][nt], A[mt], B0, B1);
            }
        }
    }
    asm volatile("cp.async.wait_group 0;" ::: "memory");
}

// -------------------- main fused kernel --------------------------------------
__global__ void __launch_bounds__(THREADS)
cin_mma(const float* __restrict__ x,
        const float* __restrict__ w0p, const float* __restrict__ w1p,
        const float* __restrict__ w2p,
        const float* __restrict__ b0, const float* __restrict__ b1,
        const float* __restrict__ b2,
        float* __restrict__ out)
{
    extern __shared__ float smf[];
    float* x0s = smf;                        // 40*XROW
    float* xis = smf + 40 * XROW;            // 128*XROW
    float* wsm = smf + (40 + 128) * XROW;    // 3 * 128*40 (layer0) / 3 * 128*32

    int tid = threadIdx.x;
    int lane = tid & 31, wid = tid >> 5;
    int grp = lane >> 2, tig = lane & 3;
    int h_base = (wid & 1) * 64, n_base = (wid >> 1) * 32;
    int bbase = blockIdx.x * NBT;
    int nb = min(NBT, 4096 - bbase);         // valid batches this CTA

    // stage X0: x[b, j, d] -> x0s[j][b*16+d]; zero row 39 and invalid columns
    for (int i = tid; i < NBT * 624; i += THREADS) {
        int b = i / 624, r = i - b * 624;
        float v = (b < nb) ? x[(size_t)(bbase + b) * 624 + r] : 0.f;
        x0s[(r >> 4) * XROW + b * 16 + (r & 15)] = v;
    }
    for (int i = tid; i < XROW; i += THREADS) x0s[39 * XROW + i] = 0.f;
    __syncthreads();

    float acc[4][4][4];

    #pragma unroll 1
    for (int l = 0; l < 3; l++) {
        #pragma unroll
        for (int mt = 0; mt < 4; mt++)
            #pragma unroll
            for (int nt = 0; nt < 4; nt++)
                #pragma unroll
                for (int q = 0; q < 4; q++) acc[mt][nt][q] = 0.f;

        const float* bias;
        if (l == 0) {
            bias = b0;
            layer_mma<40, 5, 39>(w0p, x0s, x0s, wsm, acc, tid);
        } else if (l == 1) {
            bias = b1;
            layer_mma<32, 4, 156>(w1p, xis, x0s, wsm, acc, tid);
        } else {
            bias = b2;
            layer_mma<32, 4, 156>(w2p, xis, x0s, wsm, acc, tid);
        }

        __syncthreads();   // all reads of xis done before in-place overwrite

        // write Z (+bias) into xis
        #pragma unroll
        for (int mt = 0; mt < 4; mt++) {
            int h0 = h_base + mt * 16 + grp;
            float bv0 = __ldg(bias + h0), bv1 = __ldg(bias + h0 + 8);
            #pragma unroll
            for (int nt = 0; nt < 4; nt++) {
                int n = n_base + nt * 8 + 2 * tig;
                *(float2*)(xis + h0 * XROW + n) =
                    make_float2(acc[mt][nt][0] + bv0, acc[mt][nt][1] + bv0);
                *(float2*)(xis + (h0 + 8) * XROW + n) =
                    make_float2(acc[mt][nt][2] + bv1, acc[mt][nt][3] + bv1);
            }
        }
        __syncthreads();

        // d-sums -> out  (NBT b x 128 h = 1792 rows)
        #pragma unroll
        for (int t = 0; t < 4; t++) {
            int idx = tid + THREADS * t;
            int b = idx >> 7, h = idx & 127;
            if (b < nb) {
                const float4* p4 = (const float4*)(xis + h * XROW + b * 16);
                float4 a = p4[0], c4 = p4[1], e = p4[2], g = p4[3];
                out[(size_t)(bbase + b) * 384 + l * 128 + h] =
                    (a.x + a.y + a.z + a.w) + (c4.x + c4.y + c4.z + c4.w) +
                    (e.x + e.y + e.z + e.w) + (g.x + g.y + g.z + g.w);
            }
        }
        __syncthreads();
    }
}

// -------------------- launch -------------------------------------------------
extern "C" void kernel_launch(void* const* d_in, const int* in_sizes, int n_in,
                              void* d_out, int out_size) {
    const float* x  = (const float*)d_in[0];
    const float* W0 = (const float*)d_in[1];
    const float* b0 = (const float*)d_in[2];
    const float* W1 = (const float*)d_in[3];
    const float* b1 = (const float*)d_in[4];
    const float* W2 = (const float*)d_in[5];
    const float* b2 = (const float*)d_in[6];
    float* out = (float*)d_out;

    float *w0p, *w1p, *w2p;
    cudaGetSymbolAddress((void**)&w0p, W0pg);
    cudaGetSymbolAddress((void**)&w1p, W1pg);
    cudaGetSymbolAddress((void**)&w2p, W2pg);

    frag_w0<<<(39 * 1280 + 255) / 256, 256>>>(W0);
    frag_w<<<(156 * 1024 + 255) / 256, 256>>>(W1, w1p);
    frag_w<<<(156 * 1024 + 255) / 256, 256>>>(W2, w2p);

    // smem: x0s 40*XROW + xis 128*XROW + W 3 stages of 128*40  (floats)
    int smem_bytes = ((40 + 128) * XROW + 3 * 128 * 40) * 4;   // 217,344 B
    cudaFuncSetAttribute(cin_mma, cudaFuncAttributeMaxDynamicSharedMemorySize, smem_bytes);
    int grid = (4096 + NBT - 1) / NBT;   // 293 ~= 2 full waves on 148 SMs
    cin_mma<<<grid, THREADS, smem_bytes>>>(x, w0p, w1p, w2p, b0, b1, b2, out);
}

// round 8
// speedup vs baseline: 1.0156x; 1.0156x over previous
#include <cuda_runtime.h>
#include <cstdint>

// CIN (xDeepFM) via mma.sync tf32 — round 8.
// R6 config (NBT=16, 512 thr, 16 warps, 64h x 32n warp tiles, fragment-ordered W)
// + single __syncthreads per chunk (3-stage pipe for layers 1/2, 2-stage for layer 0).

#define THREADS 512
#define NBT     16
#define XROW    264     // smem row stride (floats), mod 32 == 8 -> conflict-free

typedef unsigned long long u64;

// Fragment-ordered tf32 weights: [chunk][kstep][htile(8)][lane(32)][4]
__device__ float W0pg[39 * 5 * 8 * 32 * 4];    // layer0: CHUNK=40 (39 real + 1 pad)
__device__ float W1pg[156 * 4 * 8 * 32 * 4];   // layers 1/2: CHUNK=32
__device__ float W2pg[156 * 4 * 8 * 32 * 4];

__device__ __forceinline__ uint32_t smem_u32(const void* p) {
    uint32_t a;
    asm("{ .reg .u64 t; cvta.to.shared.u64 t, %1; cvt.u32.u64 %0, t; }" : "=r"(a) : "l"(p));
    return a;
}
__device__ __forceinline__ float tf32r(float x) {
    uint32_t u; asm("cvt.rna.tf32.f32 %0, %1;" : "=r"(u) : "f"(x));
    return __uint_as_float(u);
}
__device__ __forceinline__ void cp16(uint32_t dst, const float* src) {
    asm volatile("cp.async.cg.shared.global [%0], [%1], 16;" :: "r"(dst), "l"(src) : "memory");
}
__device__ __forceinline__ void mma8(float c[4], const uint32_t a[4], uint32_t b0, uint32_t b1) {
    asm volatile(
        "mma.sync.aligned.m16n8k8.row.col.f32.tf32.tf32.f32 "
        "{%0,%1,%2,%3},{%4,%5,%6,%7},{%8,%9},{%0,%1,%2,%3};"
        : "+f"(c[0]), "+f"(c[1]), "+f"(c[2]), "+f"(c[3])
        : "r"(a[0]), "r"(a[1]), "r"(a[2]), "r"(a[3]), "r"(b0), "r"(b1));
}

// -------------------- weight prep: fragment-order repack ---------------------
__global__ void frag_w(const float* __restrict__ W, float* __restrict__ Wo) {
    int g = blockIdx.x * 256 + threadIdx.x;
    if (g >= 156 * 1024) return;
    int lane = g & 31, ht = (g >> 5) & 7, ks = (g >> 8) & 3, c = g >> 10;
    int grp = lane >> 2, tig = lane & 3;
    int row = ht * 16 + grp;
    int col = c * 32 + ks * 8 + tig;
    float4 v;
    v.x = tf32r(W[(size_t)row * 4992 + col]);
    v.y = tf32r(W[(size_t)(row + 8) * 4992 + col]);
    v.z = tf32r(W[(size_t)row * 4992 + col + 4]);
    v.w = tf32r(W[(size_t)(row + 8) * 4992 + col + 4]);
    ((float4*)Wo)[g] = v;
}
__global__ void frag_w0(const float* __restrict__ W) {
    int g = blockIdx.x * 256 + threadIdx.x;
    if (g >= 39 * 1280) return;
    int lane = g & 31, ht = (g >> 5) & 7;
    int r = g >> 8;              // ks + 5*c
    int ks = r % 5, c = r / 5;
    int grp = lane >> 2, tig = lane & 3;
    int row = ht * 16 + grp;
    int kl = ks * 8 + tig;       // <= 35
    int col = c * 39 + kl;
    float4 v;
    v.x = tf32r(W[(size_t)row * 1521 + col]);
    v.y = tf32r(W[(size_t)(row + 8) * 1521 + col]);
    v.z = (kl + 4 < 39) ? tf32r(W[(size_t)row * 1521 + col + 4]) : 0.f;
    v.w = (kl + 4 < 39) ? tf32r(W[(size_t)(row + 8) * 1521 + col + 4]) : 0.f;
    ((float4*)W0pg)[g] = v;
}

// -------------------- chunk compute (shared by both pipelines) ---------------
template <int CHUNK, int KSTEPS>
__device__ __forceinline__ void chunk_compute(
    const float* stage, const float* xi, const float* x0s,
    int c, int n_base, int ht_base, int grp, int tig, int lane,
    float acc[4][4][4])
{
    const float4* wf = (const float4*)stage;
    int j   = (CHUNK == 40) ? c : (c >> 2);
    int kkb = (CHUNK == 40) ? 0 : ((c & 3) * 32);

    float x0v[4];
    #pragma unroll
    for (int nt = 0; nt < 4; nt++)
        x0v[nt] = x0s[j * XROW + n_base + nt * 8 + grp];

    #pragma unroll
    for (int ks = 0; ks < KSTEPS; ks++) {
        uint32_t A[4][4];
        const float4* af = wf + ((ks * 8 + ht_base) * 32 + lane);
        #pragma unroll
        for (int mt = 0; mt < 4; mt++) {
            float4 av = af[mt * 32];
            A[mt][0] = __float_as_uint(av.x);
            A[mt][1] = __float_as_uint(av.y);
            A[mt][2] = __float_as_uint(av.z);
            A[mt][3] = __float_as_uint(av.w);
        }
        int kk = kkb + ks * 8 + tig;
        const float* xlo = xi + kk * XROW + n_base + grp;
        const float* xhi = xlo + 4 * XROW;
        #pragma unroll
        for (int nt = 0; nt < 4; nt++) {
            float p0 = x0v[nt] * xlo[nt * 8];
            float p1 = x0v[nt] * xhi[nt * 8];
            uint32_t B0, B1;
            asm("cvt.rna.tf32.f32 %0, %1;" : "=r"(B0) : "f"(p0));
            asm("cvt.rna.tf32.f32 %0, %1;" : "=r"(B1) : "f"(p1));
            #pragma unroll
            for (int mt = 0; mt < 4; mt++)
                mma8(acc[mt][nt], A[mt], B0, B1);
        }
    }
}

// -------------------- layer GEMMs -------------------------------------------
// Layer 0: 2-stage pipeline (CHUNK=40), one sync per chunk.
__device__ __forceinline__ void layer0_mma(
    const float* __restrict__ Wg, const float* x0s,
    float* wsm, float acc[4][4][4], int tid)
{
    const int CHUNK = 40, KSTEPS = 5, NCH = 39, STAGE = 128 * CHUNK;
    int lane = tid & 31, wid = tid >> 5;
    int grp = lane >> 2, tig = lane & 3;
    int ht_base = (wid & 1) * 4, n_base = (wid >> 1) * 32;

    auto prefetch = [&](int c) {
        if (c < NCH) {
            uint32_t du = smem_u32(wsm + (c & 1) * STAGE);
            const float* src = Wg + (size_t)c * STAGE;
            #pragma unroll
            for (int s = tid; s < STAGE / 4; s += THREADS)
                cp16(du + (uint32_t)s * 16, src + s * 4);
        }
        asm volatile("cp.async.commit_group;" ::: "memory");
    };

    prefetch(0);
    for (int c = 0; c < NCH; c++) {
        asm volatile("cp.async.wait_group 0;" ::: "memory");   // chunk c resident
        __syncthreads();                                       // all done with c-1
        prefetch(c + 1);                                       // overwrites stage (c-1)&1
        chunk_compute<CHUNK, KSTEPS>(wsm + (c & 1) * STAGE, x0s, x0s,
                                     c, n_base, ht_base, grp, tig, lane, acc);
    }
    asm volatile("cp.async.wait_group 0;" ::: "memory");
}

// Layers 1/2: 3-stage pipeline (CHUNK=32), one sync per chunk.
__device__ __forceinline__ void layer12_mma(
    const float* __restrict__ Wg, const float* xi, const float* x0s,
    float* wsm, float acc[4][4][4], int tid)
{
    const int CHUNK = 32, KSTEPS = 4, NCH = 156, STAGE = 128 * CHUNK;
    int lane = tid & 31, wid = tid >> 5;
    int grp = lane >> 2, tig = lane & 3;
    int ht_base = (wid & 1) * 4, n_base = (wid >> 1) * 32;

    auto prefetch = [&](int c) {
        if (c < NCH) {
            uint32_t du = smem_u32(wsm + (c % 3) * STAGE);
            const float* src = Wg + (size_t)c * STAGE;
            #pragma unroll
            for (int s = tid; s < STAGE / 4; s += THREADS)
                cp16(du + (uint32_t)s * 16, src + s * 4);
        }
        asm volatile("cp.async.commit_group;" ::: "memory");
    };

    prefetch(0);
    prefetch(1);
    for (int c = 0; c < NCH; c++) {
        asm volatile("cp.async.wait_group 1;" ::: "memory");   // chunk c resident
        __syncthreads();                                       // all done with c-1
        prefetch(c + 2);                                       // overwrites stage (c-1)%3
        chunk_compute<CHUNK, KSTEPS>(wsm + (c % 3) * STAGE, xi, x0s,
                                     c, n_base, ht_base, grp, tig, lane, acc);
    }
    asm volatile("cp.async.wait_group 0;" ::: "memory");
}

// -------------------- main fused kernel --------------------------------------
__global__ void __launch_bounds__(THREADS)
cin_mma(const float* __restrict__ x,
        const float* __restrict__ w0p, const float* __restrict__ w1p,
        const float* __restrict__ w2p,
        const float* __restrict__ b0, const float* __restrict__ b1,
        const float* __restrict__ b2,
        float* __restrict__ out)
{
    extern __shared__ float smf[];
    float* x0s = smf;                        // 40*XROW
    float* xis = smf + 40 * XROW;            // 128*XROW
    float* wsm = smf + (40 + 128) * XROW;    // max(2*40, 3*32)*128 floats

    int tid = threadIdx.x;
    int lane = tid & 31, wid = tid >> 5;
    int grp = lane >> 2, tig = lane & 3;
    int h_base = (wid & 1) * 64, n_base = (wid >> 1) * 32;
    int bbase = blockIdx.x * NBT;

    // stage X0: x[b, j, d] -> x0s[j][b*16+d]; zero pad row 39
    for (int i = tid; i < NBT * 624; i += THREADS) {
        int b = i / 624, r = i - b * 624;
        x0s[(r >> 4) * XROW + b * 16 + (r & 15)] = x[(size_t)(bbase + b) * 624 + r];
    }
    for (int i = tid; i < XROW; i += THREADS) x0s[39 * XROW + i] = 0.f;
    __syncthreads();

    float acc[4][4][4];

    #pragma unroll 1
    for (int l = 0; l < 3; l++) {
        #pragma unroll
        for (int mt = 0; mt < 4; mt++)
            #pragma unroll
            for (int nt = 0; nt < 4; nt++)
                #pragma unroll
                for (int q = 0; q < 4; q++) acc[mt][nt][q] = 0.f;

        const float* bias;
        if (l == 0) {
            bias = b0;
            layer0_mma(w0p, x0s, wsm, acc, tid);
        } else if (l == 1) {
            bias = b1;
            layer12_mma(w1p, xis, x0s, wsm, acc, tid);
        } else {
            bias = b2;
            layer12_mma(w2p, xis, x0s, wsm, acc, tid);
        }

        __syncthreads();   // all reads of xis done before in-place overwrite

        // write Z (+bias) into xis
        #pragma unroll
        for (int mt = 0; mt < 4; mt++) {
            int h0 = h_base + mt * 16 + grp;
            float bv0 = __ldg(bias + h0), bv1 = __ldg(bias + h0 + 8);
            #pragma unroll
            for (int nt = 0; nt < 4; nt++) {
                int n = n_base + nt * 8 + 2 * tig;
                *(float2*)(xis + h0 * XROW + n) =
                    make_float2(acc[mt][nt][0] + bv0, acc[mt][nt][1] + bv0);
                *(float2*)(xis + (h0 + 8) * XROW + n) =
                    make_float2(acc[mt][nt][2] + bv1, acc[mt][nt][3] + bv1);
            }
        }
        __syncthreads();

        // d-sums -> out  (16 b x 128 h = 2048 rows)
        #pragma unroll
        for (int t = 0; t < 4; t++) {
            int idx = tid + THREADS * t;
            int b = idx >> 7, h = idx & 127;
            const float4* p4 = (const float4*)(xis + h * XROW + b * 16);
            float4 a = p4[0], c4 = p4[1], e = p4[2], g = p4[3];
            out[(size_t)(bbase + b) * 384 + l * 128 + h] =
                (a.x + a.y + a.z + a.w) + (c4.x + c4.y + c4.z + c4.w) +
                (e.x + e.y + e.z + e.w) + (g.x + g.y + g.z + g.w);
        }
        __syncthreads();
    }
}

// -------------------- launch -------------------------------------------------
extern "C" void kernel_launch(void* const* d_in, const int* in_sizes, int n_in,
                              void* d_out, int out_size) {
    const float* x  = (const float*)d_in[0];
    const float* W0 = (const float*)d_in[1];
    const float* b0 = (const float*)d_in[2];
    const float* W1 = (const float*)d_in[3];
    const float* b1 = (const float*)d_in[4];
    const float* W2 = (const float*)d_in[5];
    const float* b2 = (const float*)d_in[6];
    float* out = (float*)d_out;

    float *w0p, *w1p, *w2p;
    cudaGetSymbolAddress((void**)&w0p, W0pg);
    cudaGetSymbolAddress((void**)&w1p, W1pg);
    cudaGetSymbolAddress((void**)&w2p, W2pg);

    frag_w0<<<(39 * 1280 + 255) / 256, 256>>>(W0);
    frag_w<<<(156 * 1024 + 255) / 256, 256>>>(W1, w1p);
    frag_w<<<(156 * 1024 + 255) / 256, 256>>>(W2, w2p);

    // smem: x0s 40*XROW + xis 128*XROW + W stage buffer 96*128 floats
    int smem_bytes = ((40 + 128) * XROW + 96 * 128) * 4;   // 226,560 B
    cudaFuncSetAttribute(cin_mma, cudaFuncAttributeMaxDynamicSharedMemorySize, smem_bytes);
    cin_mma<<<4096 / NBT, THREADS, smem_bytes>>>(x, w0p, w1p, w2p, b0, b1, b2, out);
}

// round 9
// speedup vs baseline: 1.5660x; 1.5420x over previous
#include <cuda_runtime.h>
#include <cstdint>

// CIN (xDeepFM) via mma.sync m16n8k16 fp16 (fp32 accum) — round 9.
// NBT=16, 512 thr, 16 warps, warp tile 64h x 32n, fragment-ordered fp16 W,
// 3-stage cp.async pipeline, one sync per chunk.
// Z[h,n] = sum_{j,k} W[h, j*Fi+k] * (X0[j,n]*Xi[k,n]),  n=(b,d).

#define THREADS 512
#define NBT     16
#define XROW    260    // smem row stride (floats); mod 32 == 4 -> conflict-free B loads

typedef unsigned long long u64;

// Fragment-ordered fp16 weights: [chunk][k16step][htile(8)][lane(32)] x uint4
__device__ uint4 W0f[39 * 3 * 8 * 32];    // layer0: CHUNK=48 (39 real k + pad)
__device__ uint4 W1f[156 * 2 * 8 * 32];   // layers 1/2: CHUNK=32
__device__ uint4 W2f[156 * 2 * 8 * 32];

__device__ __forceinline__ uint32_t smem_u32(const void* p) {
    uint32_t a;
    asm("{ .reg .u64 t; cvta.to.shared.u64 t, %1; cvt.u32.u64 %0, t; }" : "=r"(a) : "l"(p));
    return a;
}
__device__ __forceinline__ uint32_t pk16(float lo, float hi) {
    uint32_t r; asm("cvt.rn.f16x2.f32 %0, %1, %2;" : "=r"(r) : "f"(hi), "f"(lo));
    return r;
}
__device__ __forceinline__ void cp16(uint32_t dst, const void* src) {
    asm volatile("cp.async.cg.shared.global [%0], [%1], 16;" :: "r"(dst), "l"(src) : "memory");
}
__device__ __forceinline__ void mma16(float c[4], const uint32_t a[4], uint32_t b0, uint32_t b1) {
    asm volatile(
        "mma.sync.aligned.m16n8k16.row.col.f32.f16.f16.f32 "
        "{%0,%1,%2,%3},{%4,%5,%6,%7},{%8,%9},{%0,%1,%2,%3};"
        : "+f"(c[0]), "+f"(c[1]), "+f"(c[2]), "+f"(c[3])
        : "r"(a[0]), "r"(a[1]), "r"(a[2]), "r"(a[3]), "r"(b0), "r"(b1));
}

// -------------------- weight prep: fp16 fragment repack -----------------------
// layers 1/2: W[128][4992], CHUNK=32 -> 2 k16 steps per chunk, NCH=156.
__global__ void frag_w(const float* __restrict__ W, uint4* __restrict__ Wo) {
    int g = blockIdx.x * 256 + threadIdx.x;
    if (g >= 156 * 512) return;
    int lane = g & 31, ht = (g >> 5) & 7, ks = (g >> 8) & 1, c = g >> 9;
    int grp = lane >> 2, tig = lane & 3;
    int r0 = ht * 16 + grp, r1 = r0 + 8;
    int kc = c * 32 + ks * 16 + 2 * tig;
    uint4 v;
    v.x = pk16(W[(size_t)r0 * 4992 + kc],     W[(size_t)r0 * 4992 + kc + 1]);
    v.y = pk16(W[(size_t)r1 * 4992 + kc],     W[(size_t)r1 * 4992 + kc + 1]);
    v.z = pk16(W[(size_t)r0 * 4992 + kc + 8], W[(size_t)r0 * 4992 + kc + 9]);
    v.w = pk16(W[(size_t)r1 * 4992 + kc + 8], W[(size_t)r1 * 4992 + kc + 9]);
    Wo[g] = v;
}
// layer0: W[128][1521], CHUNK=48 (39 real), 3 k16 steps per chunk, NCH=39.
__global__ void frag_w0(const float* __restrict__ W) {
    int g = blockIdx.x * 256 + threadIdx.x;
    if (g >= 39 * 768) return;
    int lane = g & 31, ht = (g >> 5) & 7;
    int r = g >> 8;                 // ks + 3*c
    int ks = r % 3, c = r / 3;
    int grp = lane >> 2, tig = lane & 3;
    int r0 = ht * 16 + grp, r1 = r0 + 8;
    int kp = ks * 16 + 2 * tig;     // 0..38
    const float* w0 = W + (size_t)r0 * 1521 + c * 39;
    const float* w1 = W + (size_t)r1 * 1521 + c * 39;
    auto gv = [&](const float* w, int k) { return (k < 39) ? w[k] : 0.f; };
    uint4 v;
    v.x = pk16(gv(w0, kp),     gv(w0, kp + 1));
    v.y = pk16(gv(w1, kp),     gv(w1, kp + 1));
    v.z = pk16(gv(w0, kp + 8), gv(w0, kp + 9));
    v.w = pk16(gv(w1, kp + 8), gv(w1, kp + 9));
    W0f[g] = v;
}

// -------------------- chunk compute -------------------------------------------
template <int CHUNK, int K16>
__device__ __forceinline__ void chunk_compute(
    const float* stage, const float* xi, const float* x0s,
    int c, int n_base, int ht_base, int grp, int tig,
    int lane, float acc[4][4][4])
{
    const uint4* wf = (const uint4*)stage;
    int j   = (CHUNK == 48) ? c : (c >> 2);
    int kkb = (CHUNK == 48) ? 0 : ((c & 3) * 32);

    float x0v[4];
    #pragma unroll
    for (int nt = 0; nt < 4; nt++)
        x0v[nt] = x0s[j * XROW + n_base + nt * 8 + grp];

    #pragma unroll
    for (int ks = 0; ks < K16; ks++) {
        uint32_t A[4][4];
        const uint4* af = wf + ((ks * 8 + ht_base) * 32 + lane);
        #pragma unroll
        for (int mt = 0; mt < 4; mt++) {
            uint4 av = af[mt * 32];
            A[mt][0] = av.x; A[mt][1] = av.y; A[mt][2] = av.z; A[mt][3] = av.w;
        }
        int kk = kkb + ks * 16 + 2 * tig;
        const float* xr = xi + kk * XROW;       // rows kk, kk+1, kk+8, kk+9
        #pragma unroll
        for (int nt = 0; nt < 4; nt++) {
            int n = n_base + nt * 8 + grp;
            float p0 = x0v[nt] * xr[n];
            float p1 = x0v[nt] * xr[XROW + n];
            float p2 = x0v[nt] * xr[8 * XROW + n];
            float p3 = x0v[nt] * xr[9 * XROW + n];
            uint32_t B0 = pk16(p0, p1);
            uint32_t B1 = pk16(p2, p3);
            #pragma unroll
            for (int mt = 0; mt < 4; mt++)
                mma16(acc[mt][nt], A[mt], B0, B1);
        }
    }
}

// -------------------- layer GEMM: 3-stage pipe, one sync per chunk ------------
template <int CHUNK, int K16, int NCH>
__device__ __forceinline__ void layer_mma(
    const uint4* __restrict__ Wg,
    const float* xi, const float* x0s,
    float* wsm, float acc[4][4][4], int tid)
{
    const int STAGE_B = 128 * CHUNK * 2;        // bytes per stage (fp16)
    int lane = tid & 31, wid = tid >> 5;
    int grp = lane >> 2, tig = lane & 3;
    int ht_base = (wid & 1) * 4, n_base = (wid >> 1) * 32;

    auto prefetch = [&](int c) {
        if (c < NCH) {
            uint32_t du = smem_u32((char*)wsm + (c % 3) * STAGE_B);
            const char* src = (const char*)(Wg + (size_t)c * (STAGE_B / 16));
            #pragma unroll
            for (int s = tid; s < STAGE_B / 16; s += THREADS)
                cp16(du + (uint32_t)s * 16, src + (size_t)s * 16);
        }
        asm volatile("cp.async.commit_group;" ::: "memory");
    };

    prefetch(0);
    prefetch(1);
    for (int c = 0; c < NCH; c++) {
        asm volatile("cp.async.wait_group 1;" ::: "memory");   // chunk c resident
        __syncthreads();                                       // all done with c-1
        prefetch(c + 2);                                       // overwrites stage (c-1)%3
        chunk_compute<CHUNK, K16>((const float*)((char*)wsm + (c % 3) * STAGE_B),
                                  xi, x0s, c, n_base, ht_base, grp, tig, lane, acc);
    }
    asm volatile("cp.async.wait_group 0;" ::: "memory");
}

// -------------------- main fused kernel ---------------------------------------
__global__ void __launch_bounds__(THREADS)
cin_mma(const float* __restrict__ x,
        const uint4* __restrict__ w0f, const uint4* __restrict__ w1f,
        const uint4* __restrict__ w2f,
        const float* __restrict__ b0, const float* __restrict__ b1,
        const float* __restrict__ b2,
        float* __restrict__ out)
{
    extern __shared__ float smf[];
    float* x0s = smf;                        // 48*XROW (rows 39..47 zero)
    float* xis = smf + 48 * XROW;            // 128*XROW
    float* wsm = smf + (48 + 128) * XROW;    // 3 stages x 12KB max

    int tid = threadIdx.x;
    int lane = tid & 31, wid = tid >> 5;
    int grp = lane >> 2, tig = lane & 3;
    int h_base = (wid & 1) * 64, n_base = (wid >> 1) * 32;
    int bbase = blockIdx.x * NBT;

    // stage X0: x[b, j, d] -> x0s[j][b*16+d]; zero rows 39..47
    for (int i = tid; i < NBT * 624; i += THREADS) {
        int b = i / 624, r = i - b * 624;
        x0s[(r >> 4) * XROW + b * 16 + (r & 15)] = x[(size_t)(bbase + b) * 624 + r];
    }
    for (int i = tid; i < 9 * XROW; i += THREADS) x0s[39 * XROW + i] = 0.f;
    __syncthreads();

    float acc[4][4][4];

    #pragma unroll 1
    for (int l = 0; l < 3; l++) {
        #pragma unroll
        for (int mt = 0; mt < 4; mt++)
            #pragma unroll
            for (int nt = 0; nt < 4; nt++)
                #pragma unroll
                for (int q = 0; q < 4; q++) acc[mt][nt][q] = 0.f;

        const float* bias;
        if (l == 0) {
            bias = b0;
            layer_mma<48, 3, 39>(w0f, x0s, x0s, wsm, acc, tid);
        } else if (l == 1) {
            bias = b1;
            layer_mma<32, 2, 156>(w1f, xis, x0s, wsm, acc, tid);
        } else {
            bias = b2;
            layer_mma<32, 2, 156>(w2f, xis, x0s, wsm, acc, tid);
        }

        __syncthreads();   // all reads of xis done before in-place overwrite

        // write Z (+bias) into xis
        #pragma unroll
        for (int mt = 0; mt < 4; mt++) {
            int h0 = h_base + mt * 16 + grp;
            float bv0 = __ldg(bias + h0), bv1 = __ldg(bias + h0 + 8);
            #pragma unroll
            for (int nt = 0; nt < 4; nt++) {
                int n = n_base + nt * 8 + 2 * tig;
                *(float2*)(xis + h0 * XROW + n) =
                    make_float2(acc[mt][nt][0] + bv0, acc[mt][nt][1] + bv0);
                *(float2*)(xis + (h0 + 8) * XROW + n) =
                    make_float2(acc[mt][nt][2] + bv1, acc[mt][nt][3] + bv1);
            }
        }
        __syncthreads();

        // d-sums -> out  (16 b x 128 h = 2048 rows)
        #pragma unroll
        for (int t = 0; t < 4; t++) {
            int idx = tid + THREADS * t;
            int b = idx >> 7, h = idx & 127;
            const float4* p4 = (const float4*)(xis + h * XROW + b * 16);
            float4 a = p4[0], c4 = p4[1], e = p4[2], g = p4[3];
            out[(size_t)(bbase + b) * 384 + l * 128 + h] =
                (a.x + a.y + a.z + a.w) + (c4.x + c4.y + c4.z + c4.w) +
                (e.x + e.y + e.z + e.w) + (g.x + g.y + g.z + g.w);
        }
        __syncthreads();
    }
}

// -------------------- launch ---------------------------------------------------
extern "C" void kernel_launch(void* const* d_in, const int* in_sizes, int n_in,
                              void* d_out, int out_size) {
    const float* x  = (const float*)d_in[0];
    const float* W0 = (const float*)d_in[1];
    const float* b0 = (const float*)d_in[2];
    const float* W1 = (const float*)d_in[3];
    const float* b1 = (const float*)d_in[4];
    const float* W2 = (const float*)d_in[5];
    const float* b2 = (const float*)d_in[6];
    float* out = (float*)d_out;

    uint4 *w0f, *w1f, *w2f;
    cudaGetSymbolAddress((void**)&w0f, W0f);
    cudaGetSymbolAddress((void**)&w1f, W1f);
    cudaGetSymbolAddress((void**)&w2f, W2f);

    frag_w0<<<(39 * 768 + 255) / 256, 256>>>(W0);
    frag_w<<<(156 * 512 + 255) / 256, 256>>>(W1, w1f);
    frag_w<<<(156 * 512 + 255) / 256, 256>>>(W2, w2f);

    // smem: x0s 48*XROW + xis 128*XROW + 3 stages x 12288 B
    int smem_bytes = (48 + 128) * XROW * 4 + 3 * 12288;   // 219,904 B
    cudaFuncSetAttribute(cin_mma, cudaFuncAttributeMaxDynamicSharedMemorySize, smem_bytes);
    cin_mma<<<4096 / NBT, THREADS, smem_bytes>>>(x, w0f, w1f, w2f, b0, b1, b2, out);
}

// round 10
// speedup vs baseline: 1.7691x; 1.1297x over previous
#include <cuda_runtime.h>
#include <cstdint>

// CIN (xDeepFM) via mma.sync m16n8k16 fp16 — round 10.
// fp16 k-pair-packed Xi/X0 in smem; B built with mul.f16x2; register epilogue
// (shfl d-sums + shfl-paired fp16 Z store). NBT=16, 512 thr, 64h x 32n warp tiles.

#define THREADS 512
#define NBT     16
#define XR2     264    // uint32 row stride for packed fp16 buffers; mod 32 == 8

typedef unsigned long long u64;

// Fragment-ordered fp16 weights: [chunk][k16step][htile(8)][lane(32)] x uint4
__device__ uint4 W0f[39 * 3 * 8 * 32];    // layer0: CHUNK=48 (39 real k + pad)
__device__ uint4 W1f[156 * 2 * 8 * 32];   // layers 1/2: CHUNK=32
__device__ uint4 W2f[156 * 2 * 8 * 32];

__device__ __forceinline__ uint32_t smem_u32(const void* p) {
    uint32_t a;
    asm("{ .reg .u64 t; cvta.to.shared.u64 t, %1; cvt.u32.u64 %0, t; }" : "=r"(a) : "l"(p));
    return a;
}
__device__ __forceinline__ uint32_t pk16(float lo, float hi) {
    uint32_t r; asm("cvt.rn.f16x2.f32 %0, %1, %2;" : "=r"(r) : "f"(hi), "f"(lo));
    return r;
}
__device__ __forceinline__ uint32_t hmul2(uint32_t a, uint32_t b) {
    uint32_t r; asm("mul.rn.f16x2 %0, %1, %2;" : "=r"(r) : "r"(a), "r"(b));
    return r;
}
__device__ __forceinline__ uint32_t prmt(uint32_t a, uint32_t sel) {
    uint32_t r; asm("prmt.b32 %0, %1, %2, %3;" : "=r"(r) : "r"(a), "r"(a), "r"(sel));
    return r;
}
__device__ __forceinline__ void cp16(uint32_t dst, const void* src) {
    asm volatile("cp.async.cg.shared.global [%0], [%1], 16;" :: "r"(dst), "l"(src) : "memory");
}
__device__ __forceinline__ void mma16(float c[4], const uint32_t a[4], uint32_t b0, uint32_t b1) {
    asm volatile(
        "mma.sync.aligned.m16n8k16.row.col.f32.f16.f16.f32 "
        "{%0,%1,%2,%3},{%4,%5,%6,%7},{%8,%9},{%0,%1,%2,%3};"
        : "+f"(c[0]), "+f"(c[1]), "+f"(c[2]), "+f"(c[3])
        : "r"(a[0]), "r"(a[1]), "r"(a[2]), "r"(a[3]), "r"(b0), "r"(b1));
}

// -------------------- weight prep: fp16 fragment repack (as R9) ---------------
__global__ void frag_w(const float* __restrict__ W, uint4* __restrict__ Wo) {
    int g = blockIdx.x * 256 + threadIdx.x;
    if (g >= 156 * 512) return;
    int lane = g & 31, ht = (g >> 5) & 7, ks = (g >> 8) & 1, c = g >> 9;
    int grp = lane >> 2, tig = lane & 3;
    int r0 = ht * 16 + grp, r1 = r0 + 8;
    int kc = c * 32 + ks * 16 + 2 * tig;
    uint4 v;
    v.x = pk16(W[(size_t)r0 * 4992 + kc],     W[(size_t)r0 * 4992 + kc + 1]);
    v.y = pk16(W[(size_t)r1 * 4992 + kc],     W[(size_t)r1 * 4992 + kc + 1]);
    v.z = pk16(W[(size_t)r0 * 4992 + kc + 8], W[(size_t)r0 * 4992 + kc + 9]);
    v.w = pk16(W[(size_t)r1 * 4992 + kc + 8], W[(size_t)r1 * 4992 + kc + 9]);
    Wo[g] = v;
}
__global__ void frag_w0(const float* __restrict__ W) {
    int g = blockIdx.x * 256 + threadIdx.x;
    if (g >= 39 * 768) return;
    int lane = g & 31, ht = (g >> 5) & 7;
    int r = g >> 8;                 // ks + 3*c
    int ks = r % 3, c = r / 3;
    int grp = lane >> 2, tig = lane & 3;
    int r0 = ht * 16 + grp, r1 = r0 + 8;
    int kp = ks * 16 + 2 * tig;
    const float* w0 = W + (size_t)r0 * 1521 + c * 39;
    const float* w1 = W + (size_t)r1 * 1521 + c * 39;
    auto gv = [&](const float* w, int k) { return (k < 39) ? w[k] : 0.f; };
    uint4 v;
    v.x = pk16(gv(w0, kp),     gv(w0, kp + 1));
    v.y = pk16(gv(w1, kp),     gv(w1, kp + 1));
    v.z = pk16(gv(w0, kp + 8), gv(w0, kp + 9));
    v.w = pk16(gv(w1, kp + 8), gv(w1, kp + 9));
    W0f[g] = v;
}

// -------------------- chunk compute (packed fp16 B path) ----------------------
template <int CHUNK, int K16>
__device__ __forceinline__ void chunk_compute(
    const char* stage, const uint32_t* xih, const uint32_t* x0h,
    int c, int n_base, int ht_base, int grp, int tig, int lane,
    float acc[4][4][4])
{
    const uint4* wf = (const uint4*)stage;
    int j   = (CHUNK == 48) ? c : (c >> 2);
    int k2b = (CHUNK == 48) ? 0 : ((c & 3) * 16);

    // packed duplicated x0 multiplier per n-tile (low/high half of pair word)
    uint32_t sel = (j & 1) ? 0x3232u : 0x1010u;
    const uint32_t* x0r = x0h + (j >> 1) * XR2 + n_base + grp;
    uint32_t x0p[4];
    #pragma unroll
    for (int nt = 0; nt < 4; nt++)
        x0p[nt] = prmt(x0r[nt * 8], sel);

    #pragma unroll
    for (int ks = 0; ks < K16; ks++) {
        uint32_t A[4][4];
        const uint4* af = wf + ((ks * 8 + ht_base) * 32 + lane);
        #pragma unroll
        for (int mt = 0; mt < 4; mt++) {
            uint4 av = af[mt * 32];
            A[mt][0] = av.x; A[mt][1] = av.y; A[mt][2] = av.z; A[mt][3] = av.w;
        }
        int k2 = k2b + ks * 8 + tig;                    // pair-row (kk, kk+1)
        const uint32_t* xr = xih + k2 * XR2 + n_base + grp;
        #pragma unroll
        for (int nt = 0; nt < 4; nt++) {
            uint32_t b0 = hmul2(x0p[nt], xr[nt * 8]);             // rows kk,kk+1
            uint32_t b1 = hmul2(x0p[nt], xr[4 * XR2 + nt * 8]);   // rows kk+8,kk+9
            #pragma unroll
            for (int mt = 0; mt < 4; mt++)
                mma16(acc[mt][nt], A[mt], b0, b1);
        }
    }
}

// -------------------- layer GEMM: 3-stage pipe, one sync per chunk ------------
template <int CHUNK, int K16, int NCH>
__device__ __forceinline__ void layer_mma(
    const uint4* __restrict__ Wg,
    const uint32_t* xih, const uint32_t* x0h,
    char* wsm, float acc[4][4][4], int tid)
{
    const int STAGE_B = 128 * CHUNK * 2;
    int lane = tid & 31, wid = tid >> 5;
    int grp = lane >> 2, tig = lane & 3;
    int ht_base = (wid & 1) * 4, n_base = (wid >> 1) * 32;

    auto prefetch = [&](int c) {
        if (c < NCH) {
            uint32_t du = smem_u32(wsm + (c % 3) * STAGE_B);
            const char* src = (const char*)(Wg + (size_t)c * (STAGE_B / 16));
            #pragma unroll
            for (int s = tid; s < STAGE_B / 16; s += THREADS)
                cp16(du + (uint32_t)s * 16, src + (size_t)s * 16);
        }
        asm volatile("cp.async.commit_group;" ::: "memory");
    };

    prefetch(0);
    prefetch(1);
    for (int c = 0; c < NCH; c++) {
        asm volatile("cp.async.wait_group 1;" ::: "memory");
        __syncthreads();
        prefetch(c + 2);
        chunk_compute<CHUNK, K16>(wsm + (c % 3) * STAGE_B, xih, x0h,
                                  c, n_base, ht_base, grp, tig, lane, acc);
    }
    asm volatile("cp.async.wait_group 0;" ::: "memory");
}

// -------------------- main fused kernel ---------------------------------------
__global__ void __launch_bounds__(THREADS)
cin_mma(const float* __restrict__ x,
        const uint4* __restrict__ w0f, const uint4* __restrict__ w1f,
        const uint4* __restrict__ w2f,
        const float* __restrict__ b0, const float* __restrict__ b1,
        const float* __restrict__ b2,
        float* __restrict__ out)
{
    extern __shared__ uint32_t smu[];
    uint32_t* x0h = smu;                 // 24 pair-rows x XR2 (X0 fp16 packed)
    uint32_t* xih = smu + 24 * XR2;      // 64 pair-rows x XR2 (Xi fp16 packed)
    char*     wsm = (char*)(smu + (24 + 64) * XR2);   // 3 stages x 12288 B

    int tid = threadIdx.x;
    int lane = tid & 31, wid = tid >> 5;
    int grp = lane >> 2, tig = lane & 3;
    int h_base = (wid & 1) * 64, n_base = (wid >> 1) * 32;
    int bbase = blockIdx.x * NBT;

    // build packed X0: x0h[j2][n] = (fp16 X0[2j2,n], fp16 X0[2j2+1,n]); rows>=39 zero
    for (int i = tid; i < 24 * 256; i += THREADS) {
        int j2 = i >> 8, n = i & 255;
        int b = n >> 4, d = n & 15;
        const float* xb = x + (size_t)(bbase + b) * 624 + d;
        int j0 = 2 * j2, j1 = 2 * j2 + 1;
        float f0 = (j0 < 39) ? xb[j0 * 16] : 0.f;
        float f1 = (j1 < 39) ? xb[j1 * 16] : 0.f;
        x0h[j2 * XR2 + n] = pk16(f0, f1);
    }
    __syncthreads();

    float acc[4][4][4];

    #pragma unroll 1
    for (int l = 0; l < 3; l++) {
        #pragma unroll
        for (int mt = 0; mt < 4; mt++)
            #pragma unroll
            for (int nt = 0; nt < 4; nt++)
                #pragma unroll
                for (int q = 0; q < 4; q++) acc[mt][nt][q] = 0.f;

        const float* bias;
        if (l == 0) {
            bias = b0;
            layer_mma<48, 3, 39>(w0f, x0h, x0h, wsm, acc, tid);
        } else if (l == 1) {
            bias = b1;
            layer_mma<32, 2, 156>(w1f, xih, x0h, wsm, acc, tid);
        } else {
            bias = b2;
            layer_mma<32, 2, 156>(w2f, xih, x0h, wsm, acc, tid);
        }

        __syncthreads();   // all warps done reading xih before overwrite

        // ---- register epilogue ----
        int bcol0 = (wid >> 1) * 2;   // first batch of this warp's 32 n-cols
        #pragma unroll
        for (int mt = 0; mt < 4; mt++) {
            int h0 = h_base + mt * 16 + grp;
            float bv0 = __ldg(bias + h0), bv1 = __ldg(bias + h0 + 8);

            // d-sums (exact fp32): reduce 4 cols/thread over tig (bfly)
            #pragma unroll
            for (int half = 0; half < 2; half++) {       // batch bcol0+half (nt pair)
                int nt0 = half * 2;
                float s0 = acc[mt][nt0][0] + acc[mt][nt0][1]
                         + acc[mt][nt0 + 1][0] + acc[mt][nt0 + 1][1];
                float s1 = acc[mt][nt0][2] + acc[mt][nt0][3]
                         + acc[mt][nt0 + 1][2] + acc[mt][nt0 + 1][3];
                s0 += __shfl_xor_sync(0xffffffffu, s0, 1);
                s0 += __shfl_xor_sync(0xffffffffu, s0, 2);
                s1 += __shfl_xor_sync(0xffffffffu, s1, 1);
                s1 += __shfl_xor_sync(0xffffffffu, s1, 2);
                if (tig == 0) {
                    size_t ob = (size_t)(bbase + bcol0 + half) * 384 + l * 128;
                    out[ob + h0]     = s0 + 16.f * bv0;
                    out[ob + h0 + 8] = s1 + 16.f * bv1;
                }
            }

            // fp16 Z store for next layer (skip after last layer)
            if (l < 2) {
                #pragma unroll
                for (int nt = 0; nt < 4; nt++) {
                    int n = n_base + nt * 8 + 2 * tig;
                    float v0 = acc[mt][nt][0] + bv0;   // (h0,   n)
                    float v1 = acc[mt][nt][1] + bv0;   // (h0,   n+1)
                    float v2 = acc[mt][nt][2] + bv1;   // (h0+8, n)
                    float v3 = acc[mt][nt][3] + bv1;   // (h0+8, n+1)
                    float p0 = __shfl_down_sync(0xffffffffu, v0, 4);  // odd-row partner
                    float p1 = __shfl_down_sync(0xffffffffu, v1, 4);
                    float p2 = __shfl_down_sync(0xffffffffu, v2, 4);
                    float p3 = __shfl_down_sync(0xffffffffu, v3, 4);
                    if (!(grp & 1)) {
                        uint32_t* r0 = xih + (h0 >> 1) * XR2 + n;
                        uint32_t* r1 = xih + ((h0 + 8) >> 1) * XR2 + n;
                        r0[0] = pk16(v0, p0);
                        r0[1] = pk16(v1, p1);
                        r1[0] = pk16(v2, p2);
                        r1[1] = pk16(v3, p3);
                    }
                }
            }
        }
        __syncthreads();   // xih writes visible before next layer reads
    }
}

// -------------------- launch ---------------------------------------------------
extern "C" void kernel_launch(void* const* d_in, const int* in_sizes, int n_in,
                              void* d_out, int out_size) {
    const float* x  = (const float*)d_in[0];
    const float* W0 = (const float*)d_in[1];
    const float* b0 = (const float*)d_in[2];
    const float* W1 = (const float*)d_in[3];
    const float* b1 = (const float*)d_in[4];
    const float* W2 = (const float*)d_in[5];
    const float* b2 = (const float*)d_in[6];
    float* out = (float*)d_out;

    uint4 *w0f, *w1f, *w2f;
    cudaGetSymbolAddress((void**)&w0f, W0f);
    cudaGetSymbolAddress((void**)&w1f, W1f);
    cudaGetSymbolAddress((void**)&w2f, W2f);

    frag_w0<<<(39 * 768 + 255) / 256, 256>>>(W0);
    frag_w<<<(156 * 512 + 255) / 256, 256>>>(W1, w1f);
    frag_w<<<(156 * 512 + 255) / 256, 256>>>(W2, w2f);

    // smem: x0h 24*XR2 u32 + xih 64*XR2 u32 + 3 stages x 12288 B
    int smem_bytes = (24 + 64) * XR2 * 4 + 3 * 12288;   // 129,792 B
    cudaFuncSetAttribute(cin_mma, cudaFuncAttributeMaxDynamicSharedMemorySize, smem_bytes);
    cin_mma<<<4096 / NBT, THREADS, smem_bytes>>>(x, w0f, w1f, w2f, b0, b1, b2, out);
}

// round 11
// speedup vs baseline: 2.4550x; 1.3877x over previous
#include <cuda_runtime.h>
#include <cstdint>

// CIN (xDeepFM) via mma.sync m16n8k16 fp16 — round 11.
// No W smem staging: fragment-ordered W read straight from L2 via LDG with a
// register double-buffer; ZERO intra-layer barriers. fp16-packed Xi/X0 smem,
// register epilogue (shfl d-sums + paired fp16 Z store). 512 thr, 64h x 32n tiles.

#define THREADS 512
#define NBT     16
#define XR2     264    // uint32 row stride for packed fp16 buffers; mod 32 == 8

// Fragment-ordered fp16 weights: [chunk][k16step][hgroup(2)][mtile(4)][lane(32)] uint4
__device__ uint4 W0f[39 * 3 * 2 * 4 * 32];    // layer0: CHUNK=48 (39 real k + pad)
__device__ uint4 W1f[156 * 2 * 2 * 4 * 32];   // layers 1/2: CHUNK=32
__device__ uint4 W2f[156 * 2 * 2 * 4 * 32];

__device__ __forceinline__ uint32_t pk16(float lo, float hi) {
    uint32_t r; asm("cvt.rn.f16x2.f32 %0, %1, %2;" : "=r"(r) : "f"(hi), "f"(lo));
    return r;
}
__device__ __forceinline__ uint32_t hmul2(uint32_t a, uint32_t b) {
    uint32_t r; asm("mul.rn.f16x2 %0, %1, %2;" : "=r"(r) : "r"(a), "r"(b));
    return r;
}
__device__ __forceinline__ uint32_t prmt(uint32_t a, uint32_t sel) {
    uint32_t r; asm("prmt.b32 %0, %1, %2, %3;" : "=r"(r) : "r"(a), "r"(a), "r"(sel));
    return r;
}
__device__ __forceinline__ void mma16(float c[4], const uint4 a, uint32_t b0, uint32_t b1) {
    asm volatile(
        "mma.sync.aligned.m16n8k16.row.col.f32.f16.f16.f32 "
        "{%0,%1,%2,%3},{%4,%5,%6,%7},{%8,%9},{%0,%1,%2,%3};"
        : "+f"(c[0]), "+f"(c[1]), "+f"(c[2]), "+f"(c[3])
        : "r"(a.x), "r"(a.y), "r"(a.z), "r"(a.w), "r"(b0), "r"(b1));
}

// -------------------- weight prep: fragment repack [c][ks][hg][mt][lane] -------
__global__ void frag_w(const float* __restrict__ W, uint4* __restrict__ Wo) {
    int g = blockIdx.x * 256 + threadIdx.x;
    if (g >= 156 * 512) return;
    int lane = g & 31, mt = (g >> 5) & 3, hg = (g >> 7) & 1, ks = (g >> 8) & 1, c = g >> 9;
    int grp = lane >> 2, tig = lane & 3;
    int r0 = (hg * 4 + mt) * 16 + grp, r1 = r0 + 8;
    int kc = c * 32 + ks * 16 + 2 * tig;
    uint4 v;
    v.x = pk16(W[(size_t)r0 * 4992 + kc],     W[(size_t)r0 * 4992 + kc + 1]);
    v.y = pk16(W[(size_t)r1 * 4992 + kc],     W[(size_t)r1 * 4992 + kc + 1]);
    v.z = pk16(W[(size_t)r0 * 4992 + kc + 8], W[(size_t)r0 * 4992 + kc + 9]);
    v.w = pk16(W[(size_t)r1 * 4992 + kc + 8], W[(size_t)r1 * 4992 + kc + 9]);
    Wo[g] = v;
}
__global__ void frag_w0(const float* __restrict__ W) {
    int g = blockIdx.x * 256 + threadIdx.x;
    if (g >= 39 * 768) return;
    int lane = g & 31, mt = (g >> 5) & 3, hg = (g >> 7) & 1;
    int rest = g >> 8;
    int ks = rest % 3, c = rest / 3;
    int grp = lane >> 2, tig = lane & 3;
    int r0 = (hg * 4 + mt) * 16 + grp, r1 = r0 + 8;
    int kp = ks * 16 + 2 * tig;
    const float* w0 = W + (size_t)r0 * 1521 + c * 39;
    const float* w1 = W + (size_t)r1 * 1521 + c * 39;
    auto gv = [&](const float* w, int k) { return (k < 39) ? w[k] : 0.f; };
    uint4 v;
    v.x = pk16(gv(w0, kp),     gv(w0, kp + 1));
    v.y = pk16(gv(w1, kp),     gv(w1, kp + 1));
    v.z = pk16(gv(w0, kp + 8), gv(w0, kp + 9));
    v.w = pk16(gv(w1, kp + 8), gv(w1, kp + 9));
    W0f[g] = v;
}

// -------------------- layers 1/2: barrier-free, A double-buffered -------------
__device__ __forceinline__ void layer12(
    const uint4* __restrict__ Wg,        // fragment-ordered, L2-resident
    const uint32_t* xih, const uint32_t* x0h,
    float acc[4][4][4],
    int lane, int hg, int n_base, int grp, int tig)
{
    const uint4* wp = Wg + hg * 128 + lane;   // step 0; +256 uint4 per kstep
    uint4 A[2][4];
    #pragma unroll
    for (int mt = 0; mt < 4; mt++) A[0][mt] = __ldg(wp + mt * 32);

    #pragma unroll 1
    for (int j = 0; j < 39; j++) {
        uint32_t sel = (j & 1) ? 0x3232u : 0x1010u;
        const uint32_t* x0r = x0h + (j >> 1) * XR2 + n_base + grp;
        uint32_t x0p[4];
        #pragma unroll
        for (int nt = 0; nt < 4; nt++) x0p[nt] = prmt(x0r[nt * 8], sel);

        #pragma unroll
        for (int s = 0; s < 8; s++) {            // 8 ksteps per j (parity = s&1)
            int p = s & 1;
            bool last = (j == 38) && (s == 7);
            const uint4* wn = last ? wp : (wp + 256);
            #pragma unroll
            for (int mt = 0; mt < 4; mt++) A[p ^ 1][mt] = __ldg(wn + mt * 32);
            wp = wn;

            const uint32_t* xr = xih + (s * 8 + tig) * XR2 + n_base + grp;
            #pragma unroll
            for (int nt = 0; nt < 4; nt++) {
                uint32_t b0 = hmul2(x0p[nt], xr[nt * 8]);
                uint32_t b1 = hmul2(x0p[nt], xr[4 * XR2 + nt * 8]);
                #pragma unroll
                for (int mt = 0; mt < 4; mt++)
                    mma16(acc[mt][nt], A[p][mt], b0, b1);
            }
        }
    }
}

// -------------------- layer 0: barrier-free, direct A loads -------------------
__device__ __forceinline__ void layer0(
    const uint4* __restrict__ Wg,
    const uint32_t* x0h,
    float acc[4][4][4],
    int lane, int hg, int n_base, int grp, int tig)
{
    const uint4* wp = Wg + hg * 128 + lane;

    #pragma unroll 1
    for (int j = 0; j < 39; j++) {
        uint32_t sel = (j & 1) ? 0x3232u : 0x1010u;
        const uint32_t* x0r = x0h + (j >> 1) * XR2 + n_base + grp;
        uint32_t x0p[4];
        #pragma unroll
        for (int nt = 0; nt < 4; nt++) x0p[nt] = prmt(x0r[nt * 8], sel);

        #pragma unroll
        for (int ks = 0; ks < 3; ks++) {
            uint4 A[4];
            #pragma unroll
            for (int mt = 0; mt < 4; mt++) A[mt] = __ldg(wp + mt * 32);
            wp += 256;

            const uint32_t* xr = x0h + (ks * 8 + tig) * XR2 + n_base + grp;
            #pragma unroll
            for (int nt = 0; nt < 4; nt++) {
                uint32_t b0 = hmul2(x0p[nt], xr[nt * 8]);
                uint32_t b1 = hmul2(x0p[nt], xr[4 * XR2 + nt * 8]);
                #pragma unroll
                for (int mt = 0; mt < 4; mt++)
                    mma16(acc[mt][nt], A[mt], b0, b1);
            }
        }
    }
}

// -------------------- main fused kernel ---------------------------------------
__global__ void __launch_bounds__(THREADS)
cin_mma(const float* __restrict__ x,
        const uint4* __restrict__ w0f, const uint4* __restrict__ w1f,
        const uint4* __restrict__ w2f,
        const float* __restrict__ b0, const float* __restrict__ b1,
        const float* __restrict__ b2,
        float* __restrict__ out)
{
    extern __shared__ uint32_t smu[];
    uint32_t* x0h = smu;                 // 24 pair-rows x XR2 (X0 fp16, rows>=39 zero)
    uint32_t* xih = smu + 24 * XR2;      // 64 pair-rows x XR2 (Xi fp16)

    int tid = threadIdx.x;
    int lane = tid & 31, wid = tid >> 5;
    int grp = lane >> 2, tig = lane & 3;
    int hg = wid & 1;                    // h half: h_base = hg*64
    int h_base = hg * 64, n_base = (wid >> 1) * 32;
    int bbase = blockIdx.x * NBT;

    // build packed X0: x0h[j2][n] = (fp16 X0[2j2,n], fp16 X0[2j2+1,n])
    for (int i = tid; i < 24 * 256; i += THREADS) {
        int j2 = i >> 8, n = i & 255;
        int b = n >> 4, d = n & 15;
        const float* xb = x + (size_t)(bbase + b) * 624 + d;
        int j0 = 2 * j2, j1 = 2 * j2 + 1;
        float f0 = (j0 < 39) ? xb[j0 * 16] : 0.f;
        float f1 = (j1 < 39) ? xb[j1 * 16] : 0.f;
        x0h[j2 * XR2 + n] = pk16(f0, f1);
    }
    __syncthreads();

    float acc[4][4][4];

    #pragma unroll 1
    for (int l = 0; l < 3; l++) {
        #pragma unroll
        for (int mt = 0; mt < 4; mt++)
            #pragma unroll
            for (int nt = 0; nt < 4; nt++)
                #pragma unroll
                for (int q = 0; q < 4; q++) acc[mt][nt][q] = 0.f;

        const float* bias;
        if (l == 0) {
            bias = b0;
            layer0(w0f, x0h, acc, lane, hg, n_base, grp, tig);
        } else if (l == 1) {
            bias = b1;
            layer12(w1f, xih, x0h, acc, lane, hg, n_base, grp, tig);
        } else {
            bias = b2;
            layer12(w2f, xih, x0h, acc, lane, hg, n_base, grp, tig);
        }

        __syncthreads();   // all warps done reading xih before overwrite

        // ---- register epilogue ----
        int bcol0 = (wid >> 1) * 2;   // first batch of this warp's 32 n-cols
        #pragma unroll
        for (int mt = 0; mt < 4; mt++) {
            int h0 = h_base + mt * 16 + grp;
            float bv0 = __ldg(bias + h0), bv1 = __ldg(bias + h0 + 8);

            // d-sums (exact fp32): reduce 4 cols/thread over tig (bfly)
            #pragma unroll
            for (int half = 0; half < 2; half++) {
                int nt0 = half * 2;
                float s0 = acc[mt][nt0][0] + acc[mt][nt0][1]
                         + acc[mt][nt0 + 1][0] + acc[mt][nt0 + 1][1];
                float s1 = acc[mt][nt0][2] + acc[mt][nt0][3]
                         + acc[mt][nt0 + 1][2] + acc[mt][nt0 + 1][3];
                s0 += __shfl_xor_sync(0xffffffffu, s0, 1);
                s0 += __shfl_xor_sync(0xffffffffu, s0, 2);
                s1 += __shfl_xor_sync(0xffffffffu, s1, 1);
                s1 += __shfl_xor_sync(0xffffffffu, s1, 2);
                if (tig == 0) {
                    size_t ob = (size_t)(bbase + bcol0 + half) * 384 + l * 128;
                    out[ob + h0]     = s0 + 16.f * bv0;
                    out[ob + h0 + 8] = s1 + 16.f * bv1;
                }
            }

            // fp16 Z store for next layer
            if (l < 2) {
                #pragma unroll
                for (int nt = 0; nt < 4; nt++) {
                    int n = n_base + nt * 8 + 2 * tig;
                    float v0 = acc[mt][nt][0] + bv0;
                    float v1 = acc[mt][nt][1] + bv0;
                    float v2 = acc[mt][nt][2] + bv1;
                    float v3 = acc[mt][nt][3] + bv1;
                    float p0 = __shfl_down_sync(0xffffffffu, v0, 4);
                    float p1 = __shfl_down_sync(0xffffffffu, v1, 4);
                    float p2 = __shfl_down_sync(0xffffffffu, v2, 4);
                    float p3 = __shfl_down_sync(0xffffffffu, v3, 4);
                    if (!(grp & 1)) {
                        uint32_t* r0 = xih + (h0 >> 1) * XR2 + n;
                        uint32_t* r1 = xih + ((h0 + 8) >> 1) * XR2 + n;
                        r0[0] = pk16(v0, p0);
                        r0[1] = pk16(v1, p1);
                        r1[0] = pk16(v2, p2);
                        r1[1] = pk16(v3, p3);
                    }
                }
            }
        }
        __syncthreads();   // xih writes visible before next layer reads
    }
}

// -------------------- launch ---------------------------------------------------
extern "C" void kernel_launch(void* const* d_in, const int* in_sizes, int n_in,
                              void* d_out, int out_size) {
    const float* x  = (const float*)d_in[0];
    const float* W0 = (const float*)d_in[1];
    const float* b0 = (const float*)d_in[2];
    const float* W1 = (const float*)d_in[3];
    const float* b1 = (const float*)d_in[4];
    const float* W2 = (const float*)d_in[5];
    const float* b2 = (const float*)d_in[6];
    float* out = (float*)d_out;

    uint4 *w0f, *w1f, *w2f;
    cudaGetSymbolAddress((void**)&w0f, W0f);
    cudaGetSymbolAddress((void**)&w1f, W1f);
    cudaGetSymbolAddress((void**)&w2f, W2f);

    frag_w0<<<(39 * 768 + 255) / 256, 256>>>(W0);
    frag_w<<<(156 * 512 + 255) / 256, 256>>>(W1, w1f);
    frag_w<<<(156 * 512 + 255) / 256, 256>>>(W2, w2f);

    // smem: x0h 24*XR2 + xih 64*XR2 (uint32)
    int smem_bytes = (24 + 64) * XR2 * 4;   // 92,928 B
    cudaFuncSetAttribute(cin_mma, cudaFuncAttributeMaxDynamicSharedMemorySize, smem_bytes);
    cin_mma<<<4096 / NBT, THREADS, smem_bytes>>>(x, w0f, w1f, w2f, b0, b1, b2, out);
}